// round 2
// baseline (speedup 1.0000x reference)
#include <cuda_runtime.h>

// ConvolutionalSocialPooling fused kernel.
// One block per batch element. Stages:
//  1) winner-per-cell via smem integer atomicMax (deterministic)
//  2) gather winner vehicle's last-timestep features into smem
//  3) conv3x1 (skip empty cells; bitwise == dense since empty cells are exact 0)
//  4) conv1x1 + lrelu + 3x3/3 maxpool fused
//  5) 160->64 FC + lrelu
namespace {

constexpr int GRID_H = 13;
constexpr int GRID_W = 3;
constexpr int G      = GRID_H * GRID_W;   // 39
constexpr int ENC    = 128;
constexpr int TS     = 16;
constexpr int C31    = 16;
constexpr int SOCD   = 64;
constexpr int KN     = 32;
constexpr int FPITCH = 129;               // feat row pitch (bank-conflict-free)

__device__ __forceinline__ float lrelu(float x) { return x > 0.0f ? x : 0.1f * x; }

__global__ __launch_bounds__(256, 4)
void csp_kernel(const float* __restrict__ enc,   // [N_VEH,128,16]
                const int*   __restrict__ nb,    // [B,32]
                const int*   __restrict__ gp,    // [N_VEH,2]
                const float* __restrict__ w31,   // [16,128,3,1]
                const float* __restrict__ b31,   // [16]
                const float* __restrict__ w11,   // [32,16,1,1]
                const float* __restrict__ b11,   // [32]
                const float* __restrict__ fcw,   // [64,160]
                const float* __restrict__ fcb,   // [64]
                float*       __restrict__ out)   // [B,64]
{
    __shared__ __align__(16) float wsA[3 * ENC * C31];  // [kh][ic][oc]  24 KB
    __shared__ __align__(16) float feat[G * FPITCH];    // ~20 KB
    __shared__ __align__(16) float a1[G * C31];         // conv31 activations
    __shared__ __align__(16) float p[160];              // pooled, flatten order oc2*5+ph
    __shared__ int winner[G];
    __shared__ int veh[G];

    const int b   = blockIdx.x;
    const int tid = threadIdx.x;

    // ---- load & transpose conv3x1 weights: wsA[kh*2048 + ic*16 + oc] ----
    for (int i = tid; i < 3 * ENC * C31; i += 256) {
        int kh = i >> 11;
        int r  = i & 2047;
        int ic = r >> 4, oc = r & 15;
        wsA[i] = w31[(oc * ENC + ic) * 3 + kh];
    }
    if (tid < G) winner[tid] = -1;
    __syncthreads();

    // ---- winner per cell (max neighbor slot id) ----
    if (tid < KN) {
        int v = nb[b * KN + tid];
        int x = gp[2 * v], y = gp[2 * v + 1];
        if (x >= 0 && x < GRID_H && y >= 0 && y < GRID_W)
            atomicMax(&winner[x * GRID_W + y], tid);
    }
    __syncthreads();
    if (tid < G) {
        int w = winner[tid];
        veh[tid] = (w >= 0) ? nb[b * KN + w] : -1;
    }
    __syncthreads();

    // ---- gather last-timestep features of winners ----
    for (int i = tid; i < G * ENC; i += 256) {
        int c = i >> 7, ic = i & 127;
        int v = veh[c];
        if (v >= 0)
            feat[c * FPITCH + ic] = __ldg(enc + (size_t)v * (ENC * TS) + ic * TS + (TS - 1));
    }
    __syncthreads();

    // ---- conv3x1 + bias + lrelu.  156 tasks: (pos 0..38) x (ocg 0..3) ----
    if (tid < G * 4) {
        int pos = tid >> 2, ocg = tid & 3;
        int h = pos / 3, w = pos - h * 3;
        float4 acc = *(const float4*)(b31 + ocg * 4);
        #pragma unroll
        for (int kh = 0; kh < 3; ++kh) {
            int hh = h - 1 + kh;
            if (hh < 0 || hh >= GRID_H) continue;
            int cell = hh * 3 + w;
            if (veh[cell] < 0) continue;           // empty cell: exact zero contribution
            const float*  fr = feat + cell * FPITCH;
            const float4* wr = (const float4*)(wsA + (kh << 11)) + ocg;
            #pragma unroll 4
            for (int ic = 0; ic < ENC; ++ic) {
                float  f  = fr[ic];
                float4 wv = wr[ic * 4];
                acc.x += f * wv.x; acc.y += f * wv.y;
                acc.z += f * wv.z; acc.w += f * wv.w;
            }
        }
        float* ao = a1 + pos * C31 + ocg * 4;
        ao[0] = lrelu(acc.x); ao[1] = lrelu(acc.y);
        ao[2] = lrelu(acc.z); ao[3] = lrelu(acc.w);
    }
    __syncthreads();

    // ---- conv1x1 + lrelu fused with 3x3/3 maxpool (H padded 0,2) ----
    // task = oc2*5 + ph  (== flatten index)
    if (tid < 160) {
        int oc2 = tid / 5, ph = tid - oc2 * 5;
        float wr[16];
        #pragma unroll
        for (int ic = 0; ic < 16; ++ic) wr[ic] = __ldg(w11 + oc2 * 16 + ic);
        float bias = __ldg(b11 + oc2);
        float m = -3.4e38f;
        int h1 = min(3 * ph + 3, GRID_H);
        for (int h = 3 * ph; h < h1; ++h) {
            #pragma unroll
            for (int w = 0; w < 3; ++w) {
                const float* ar = a1 + (h * 3 + w) * C31;
                float s = bias;
                #pragma unroll
                for (int ic = 0; ic < 16; ++ic) s += ar[ic] * wr[ic];
                m = fmaxf(m, lrelu(s));
            }
        }
        p[tid] = m;
    }
    __syncthreads();

    // ---- FC 160 -> 64 + lrelu ----
    if (tid < SOCD) {
        float acc = __ldg(fcb + tid);
        const float4* wr = (const float4*)(fcw + tid * 160);
        const float4* pr = (const float4*)p;
        #pragma unroll 8
        for (int f = 0; f < 40; ++f) {
            float4 wv = __ldg(wr + f);
            float4 pv = pr[f];
            acc += wv.x * pv.x + wv.y * pv.y + wv.z * pv.z + wv.w * pv.w;
        }
        out[b * SOCD + tid] = lrelu(acc);
    }
}

} // namespace

extern "C" void kernel_launch(void* const* d_in, const int* in_sizes, int n_in,
                              void* d_out, int out_size)
{
    const float* enc = (const float*)d_in[0];
    const int*   nb  = (const int*)  d_in[1];
    const int*   gp  = (const int*)  d_in[2];
    const float* w31 = (const float*)d_in[3];
    const float* b31 = (const float*)d_in[4];
    const float* w11 = (const float*)d_in[5];
    const float* b11 = (const float*)d_in[6];
    const float* fcw = (const float*)d_in[7];
    const float* fcb = (const float*)d_in[8];
    float* out = (float*)d_out;

    const int batch = in_sizes[1] / KN;   // 8192
    csp_kernel<<<batch, 256>>>(enc, nb, gp, w31, b31, w11, b11, fcw, fcb, out);
}

// round 3
// speedup vs baseline: 1.1065x; 1.1065x over previous
#include <cuda_runtime.h>

// ConvolutionalSocialPooling fused kernel, round 3.
//  - prep kernel pre-transposes conv3x1 weights into __device__ global wT
//    (kills per-block scattered weight staging: ~6144 L1 wavefronts/block -> 0)
//  - main kernel: compact occupied-cell gather, conv reads weights via L1-resident
//    __ldg float4 broadcast, smem halved -> higher occupancy.
namespace {

constexpr int GRID_H = 13;
constexpr int GRID_W = 3;
constexpr int G      = GRID_H * GRID_W;   // 39
constexpr int ENC    = 128;
constexpr int TS     = 16;
constexpr int C31    = 16;
constexpr int SOCD   = 64;
constexpr int KN     = 32;
constexpr int FPITCH = 129;               // feat row pitch (bank-conflict-free)

__device__ __align__(16) float wT[3 * ENC * C31];   // [kh][ic][oc16]

__device__ __forceinline__ float lrelu(float x) { return x > 0.0f ? x : 0.1f * x; }

__global__ void prep_kernel(const float* __restrict__ w31)
{
    int i = blockIdx.x * 256 + threadIdx.x;
    if (i < 3 * ENC * C31) {
        int kh = i >> 11;
        int r  = i & 2047;
        int ic = r >> 4, oc = r & 15;
        wT[i] = w31[(oc * ENC + ic) * 3 + kh];
    }
}

__global__ __launch_bounds__(256, 6)
void csp_kernel(const float* __restrict__ enc,   // [N_VEH,128,16]
                const int*   __restrict__ nb,    // [B,32]
                const int*   __restrict__ gp,    // [N_VEH,2]
                const float* __restrict__ b31,   // [16]
                const float* __restrict__ w11,   // [32,16]
                const float* __restrict__ b11,   // [32]
                const float* __restrict__ fcw,   // [64,160]
                const float* __restrict__ fcb,   // [64]
                float*       __restrict__ out)   // [B,64]
{
    __shared__ __align__(16) float feat[G * FPITCH];    // ~20 KB
    __shared__ __align__(16) float a1[G * C31];         // conv31 activations
    __shared__ __align__(16) float p[160];              // pooled, flatten order oc2*5+ph
    __shared__ int winner[G];
    __shared__ int veh[G];
    __shared__ int occ[G];
    __shared__ int nOcc;

    const int b   = blockIdx.x;
    const int tid = threadIdx.x;

    if (tid < G) winner[tid] = -1;
    if (tid == 0) nOcc = 0;
    __syncthreads();

    // ---- winner per cell (max neighbor slot id) ----
    if (tid < KN) {
        int v = nb[b * KN + tid];
        int x = gp[2 * v], y = gp[2 * v + 1];
        if (x >= 0 && x < GRID_H && y >= 0 && y < GRID_W)
            atomicMax(&winner[x * GRID_W + y], tid);
    }
    __syncthreads();
    if (tid < G) {
        int w = winner[tid];
        int v = (w >= 0) ? nb[b * KN + w] : -1;
        veh[tid] = v;
        if (v >= 0) {
            int s = atomicAdd(&nOcc, 1);
            occ[s] = tid;                         // unordered; gather target is by cell id
        }
    }
    __syncthreads();

    // ---- gather last-timestep features of winners (occupied cells only) ----
    const int total = nOcc * ENC;
    for (int i = tid; i < total; i += 256) {
        int s = i >> 7, ic = i & 127;
        int c = occ[s];
        int v = veh[c];
        feat[c * FPITCH + ic] = __ldg(enc + (size_t)v * (ENC * TS) + ic * TS + (TS - 1));
    }
    __syncthreads();

    // ---- conv3x1 + bias + lrelu.  156 tasks: (pos 0..38) x (ocg 0..3) ----
    if (tid < G * 4) {
        int pos = tid >> 2, ocg = tid & 3;
        int h = pos / 3, w = pos - h * 3;
        float4 acc = *(const float4*)(b31 + ocg * 4);
        #pragma unroll
        for (int kh = 0; kh < 3; ++kh) {
            int hh = h - 1 + kh;
            if (hh < 0 || hh >= GRID_H) continue;
            int cell = hh * 3 + w;
            if (veh[cell] < 0) continue;           // empty cell: exact zero contribution
            const float*  fr = feat + cell * FPITCH;
            const float4* wr = (const float4*)wT + (kh << 9) + ocg;  // [kh][ic][ocg4]
            #pragma unroll 4
            for (int ic = 0; ic < ENC; ++ic) {
                float  f  = fr[ic];
                float4 wv = __ldg(wr + ic * 4);
                acc.x += f * wv.x; acc.y += f * wv.y;
                acc.z += f * wv.z; acc.w += f * wv.w;
            }
        }
        float* ao = a1 + pos * C31 + ocg * 4;
        ao[0] = lrelu(acc.x); ao[1] = lrelu(acc.y);
        ao[2] = lrelu(acc.z); ao[3] = lrelu(acc.w);
    }
    __syncthreads();

    // ---- conv1x1 + lrelu fused with 3x3/3 maxpool (H padded 0,2) ----
    // task = oc2*5 + ph  (== flatten index)
    if (tid < 160) {
        int oc2 = tid / 5, ph = tid - oc2 * 5;
        float wr[16];
        #pragma unroll
        for (int ic = 0; ic < 16; ++ic) wr[ic] = __ldg(w11 + oc2 * 16 + ic);
        float bias = __ldg(b11 + oc2);
        float m = -3.4e38f;
        int h1 = min(3 * ph + 3, GRID_H);
        for (int h = 3 * ph; h < h1; ++h) {
            #pragma unroll
            for (int w = 0; w < 3; ++w) {
                const float* ar = a1 + (h * 3 + w) * C31;
                float s = bias;
                #pragma unroll
                for (int ic = 0; ic < 16; ++ic) s += ar[ic] * wr[ic];
                m = fmaxf(m, lrelu(s));
            }
        }
        p[tid] = m;
    }
    __syncthreads();

    // ---- FC 160 -> 64 + lrelu ----
    if (tid < SOCD) {
        float acc = __ldg(fcb + tid);
        const float4* wr = (const float4*)(fcw + tid * 160);
        const float4* pr = (const float4*)p;
        #pragma unroll 8
        for (int f = 0; f < 40; ++f) {
            float4 wv = __ldg(wr + f);
            float4 pv = pr[f];
            acc += wv.x * pv.x + wv.y * pv.y + wv.z * pv.z + wv.w * pv.w;
        }
        out[b * SOCD + tid] = lrelu(acc);
    }
}

} // namespace

extern "C" void kernel_launch(void* const* d_in, const int* in_sizes, int n_in,
                              void* d_out, int out_size)
{
    const float* enc = (const float*)d_in[0];
    const int*   nb  = (const int*)  d_in[1];
    const int*   gp  = (const int*)  d_in[2];
    const float* w31 = (const float*)d_in[3];
    const float* b31 = (const float*)d_in[4];
    const float* w11 = (const float*)d_in[5];
    const float* b11 = (const float*)d_in[6];
    const float* fcw = (const float*)d_in[7];
    const float* fcb = (const float*)d_in[8];
    float* out = (float*)d_out;

    const int batch = in_sizes[1] / KN;   // 8192

    prep_kernel<<<(3 * ENC * C31 + 255) / 256, 256>>>(w31);
    csp_kernel<<<batch, 256>>>(enc, nb, gp, b31, w11, b11, fcw, fcb, out);
}

// round 4
// speedup vs baseline: 1.4896x; 1.3463x over previous
#include <cuda_runtime.h>

// Round 4: sparsity-proportional conv.
//  - conv3x1 computed as per-occupied-slot kh-partials (dense tasks, no divergence),
//    then deterministic fixed-order assembly into a1.
//  - 2 batches per block to keep warps fed across the short stages.
namespace {

constexpr int GRID_H = 13;
constexpr int GRID_W = 3;
constexpr int G      = GRID_H * GRID_W;   // 39
constexpr int ENC    = 128;
constexpr int TS     = 16;
constexpr int C31    = 16;
constexpr int SOCD   = 64;
constexpr int KN     = 32;
constexpr int FPITCH = 129;
constexpr int MAXS   = 32;                // nOcc <= KN

__device__ __align__(16) float wT[3 * ENC * C31];   // [kh][ic][oc16]

__device__ __forceinline__ float lrelu(float x) { return x > 0.0f ? x : 0.1f * x; }

__global__ void prep_kernel(const float* __restrict__ w31)
{
    int i = blockIdx.x * 256 + threadIdx.x;
    if (i < 3 * ENC * C31) {
        int kh = i >> 11;
        int r  = i & 2047;
        int ic = r >> 4, oc = r & 15;
        wT[i] = w31[(oc * ENC + ic) * 3 + kh];
    }
}

__global__ __launch_bounds__(256, 4)
void csp_kernel(const float* __restrict__ enc,   // [N_VEH,128,16]
                const int*   __restrict__ nb,    // [B,32]
                const int*   __restrict__ gp,    // [N_VEH,2]
                const float* __restrict__ b31,   // [16]
                const float* __restrict__ w11,   // [32,16]
                const float* __restrict__ b11,   // [32]
                const float* __restrict__ fcw,   // [64,160]
                const float* __restrict__ fcb,   // [64]
                float*       __restrict__ out,   // [B,64]
                int batch)
{
    __shared__ __align__(16) float featC[2 * MAXS * FPITCH];  // ~33 KB
    __shared__ __align__(16) float y[2 * MAXS * 3 * C31];     // 12 KB  kh-partials
    __shared__ __align__(16) float a1[2 * G * C31];           // ~5 KB
    __shared__ __align__(16) float p[2 * 160];
    __shared__ int winner[2 * G];
    __shared__ int slotOf[2 * G];
    __shared__ int vehS[2 * MAXS];
    __shared__ int nOccS[2];

    const int b0  = blockIdx.x * 2;
    const int tid = threadIdx.x;

    if (tid < 2 * G) { winner[tid] = -1; slotOf[tid] = -1; }
    if (tid < 2) nOccS[tid] = 0;
    __syncthreads();

    // ---- winners (max neighbor slot id per cell), both batches ----
    if (tid < 2 * KN) {
        int u = tid >> 5, k = tid & 31;
        int b = b0 + u;
        if (b < batch) {
            int v = nb[b * KN + k];
            int x = gp[2 * v], yy = gp[2 * v + 1];
            if (x >= 0 && x < GRID_H && yy >= 0 && yy < GRID_W)
                atomicMax(&winner[u * G + x * GRID_W + yy], k);
        }
    }
    __syncthreads();

    // ---- compact occupied cells into slots ----
    if (tid < 2 * G) {
        int u = tid >= G ? 1 : 0;
        int w = winner[tid];
        if (w >= 0) {
            int v = nb[(b0 + u) * KN + w];
            int s = atomicAdd(&nOccS[u], 1);
            vehS[u * MAXS + s] = v;
            slotOf[tid] = s;
        }
    }
    __syncthreads();
    const int n0 = nOccS[0], n1 = nOccS[1];

    // ---- gather last-timestep features (occupied slots only) ----
    const int totg = (n0 + n1) << 7;
    for (int i = tid; i < totg; i += 256) {
        int g = i >> 7, ic = i & 127;
        int u = g >= n0;
        int s = g - (u ? n0 : 0);
        int v = vehS[u * MAXS + s];
        featC[(u * MAXS + s) * FPITCH + ic] =
            __ldg(enc + (size_t)v * (ENC * TS) + ic * TS + (TS - 1));
    }
    __syncthreads();

    // ---- conv3x1 kh-partials: task = (slot g, kh, ocg). No bias, no lrelu. ----
    const int ntask = (n0 + n1) * 12;
    for (int t = tid; t < ntask; t += 256) {
        int g   = t / 12;
        int r   = t - g * 12;
        int kh  = r >> 2, ocg = r & 3;
        int u   = g >= n0;
        int s   = g - (u ? n0 : 0);
        const float*  fr = featC + (u * MAXS + s) * FPITCH;
        const float4* wr = (const float4*)wT + (kh << 9) + ocg;   // [kh][ic][ocg4]
        float4 acc = make_float4(0.f, 0.f, 0.f, 0.f);
        #pragma unroll 4
        for (int ic = 0; ic < ENC; ++ic) {
            float  f  = fr[ic];
            float4 wv = __ldg(wr + ic * 4);
            acc.x += f * wv.x; acc.y += f * wv.y;
            acc.z += f * wv.z; acc.w += f * wv.w;
        }
        float* yo = y + (((u * MAXS + s) * 3 + kh) << 4) + (ocg << 2);
        yo[0] = acc.x; yo[1] = acc.y; yo[2] = acc.z; yo[3] = acc.w;
    }
    __syncthreads();

    // ---- assemble a1[pos][oc] = lrelu(bias + sum_kh partials), fixed hh order ----
    for (int e = tid; e < 2 * G * C31; e += 256) {
        int u   = e >= G * C31;
        int r   = e - (u ? G * C31 : 0);
        int pos = r >> 4, oc = r & 15;
        int h = pos / 3, w = pos - h * 3;
        float val = __ldg(b31 + oc);
        #pragma unroll
        for (int dh = -1; dh <= 1; ++dh) {
            int hh = h + dh;
            if ((unsigned)hh < (unsigned)GRID_H) {
                int s = slotOf[u * G + hh * 3 + w];
                if (s >= 0) {
                    int kh = dh + 1;
                    val += y[(((u * MAXS + s) * 3 + kh) << 4) + oc];
                }
            }
        }
        a1[e] = lrelu(val);
    }
    __syncthreads();

    // ---- conv1x1 + lrelu fused with 3x3/3 maxpool; task = u*160 + oc2*5 + ph ----
    for (int t = tid; t < 320; t += 256) {
        int u   = t >= 160;
        int r   = t - (u ? 160 : 0);
        int oc2 = r / 5, ph = r - oc2 * 5;
        float wr[16];
        #pragma unroll
        for (int ic = 0; ic < 16; ++ic) wr[ic] = __ldg(w11 + oc2 * 16 + ic);
        float bias = __ldg(b11 + oc2);
        float m = -3.4e38f;
        int h1 = min(3 * ph + 3, GRID_H);
        for (int h = 3 * ph; h < h1; ++h) {
            #pragma unroll
            for (int w = 0; w < 3; ++w) {
                const float* ar = a1 + (u ? G * C31 : 0) + (h * 3 + w) * C31;
                float s = bias;
                #pragma unroll
                for (int ic = 0; ic < 16; ++ic) s += ar[ic] * wr[ic];
                m = fmaxf(m, lrelu(s));
            }
        }
        p[t] = m;
    }
    __syncthreads();

    // ---- FC 160 -> 64 + lrelu, both batches ----
    if (tid < 2 * SOCD) {
        int u = tid >> 6, o = tid & 63;
        int b = b0 + u;
        if (b < batch) {
            float acc = __ldg(fcb + o);
            const float4* wr = (const float4*)(fcw + o * 160);
            const float4* pr = (const float4*)(p + u * 160);
            #pragma unroll 8
            for (int f = 0; f < 40; ++f) {
                float4 wv = __ldg(wr + f);
                float4 pv = pr[f];
                acc += wv.x * pv.x + wv.y * pv.y + wv.z * pv.z + wv.w * pv.w;
            }
            out[b * SOCD + o] = lrelu(acc);
        }
    }
}

} // namespace

extern "C" void kernel_launch(void* const* d_in, const int* in_sizes, int n_in,
                              void* d_out, int out_size)
{
    const float* enc = (const float*)d_in[0];
    const int*   nb  = (const int*)  d_in[1];
    const int*   gp  = (const int*)  d_in[2];
    const float* w31 = (const float*)d_in[3];
    const float* b31 = (const float*)d_in[4];
    const float* w11 = (const float*)d_in[5];
    const float* b11 = (const float*)d_in[6];
    const float* fcw = (const float*)d_in[7];
    const float* fcb = (const float*)d_in[8];
    float* out = (float*)d_out;

    const int batch = in_sizes[1] / KN;   // 8192

    prep_kernel<<<(3 * ENC * C31 + 255) / 256, 256>>>(w31);
    csp_kernel<<<(batch + 1) / 2, 256>>>(enc, nb, gp, b31, w11, b11, fcw, fcb, out, batch);
}

// round 6
// speedup vs baseline: 1.8798x; 1.2619x over previous
#include <cuda_runtime.h>

// Round 6: round-5 structure with the w11s staging bug fixed
// (512-entry stage needs a strided loop under blockDim=256).
//  - conv3x1: lane=slot, warp=(kh,ocg); weight LDG uniform (1 sector/iter).
//  - 4 batches/block, global slot pool, 32-slot smem tiles (worst-case safe).
//  - FC reads transposed fcwT -> 1 line per warp-iter (was 32).
//  - conv1x1 with smem-staged transposed w11; pool over z buffer.
//  - smem unions (featC|a1, winner|y|z) keep static smem < 48KB -> 4 blocks/SM.
namespace {

constexpr int GRID_H = 13;
constexpr int GRID_W = 3;
constexpr int G      = GRID_H * GRID_W;   // 39
constexpr int ENC    = 128;
constexpr int TS     = 16;
constexpr int C31    = 16;
constexpr int C11    = 32;
constexpr int SOCD   = 64;
constexpr int KN     = 32;
constexpr int U      = 4;                 // batches per block
constexpr int FPITCH = 129;
constexpr int MAXJ   = U * KN;            // 128 worst-case slots per block
constexpr int FCD    = 160;

__device__ __align__(16) float wT[3 * ENC * C31];     // [kh][ic][oc16]
__device__ __align__(16) float fcwT[FCD * SOCD];      // [f][o]

__device__ __forceinline__ float lrelu(float x) { return x > 0.0f ? x : 0.1f * x; }

__global__ void prep_kernel(const float* __restrict__ w31,
                            const float* __restrict__ fcw)
{
    int i = blockIdx.x * 256 + threadIdx.x;
    if (i < 3 * ENC * C31) {
        int kh = i >> 11;
        int r  = i & 2047;
        int ic = r >> 4, oc = r & 15;
        wT[i] = w31[(oc * ENC + ic) * 3 + kh];
    }
    if (i < FCD * SOCD) {
        int f = i >> 6, o = i & 63;
        fcwT[i] = fcw[o * FCD + f];
    }
}

__global__ __launch_bounds__(256, 4)
void csp_kernel(const float* __restrict__ enc,   // [N_VEH,128,16]
                const int*   __restrict__ nb,    // [B,32]
                const int*   __restrict__ gp,    // [N_VEH,2]
                const float* __restrict__ b31,   // [16]
                const float* __restrict__ w11,   // [32,16]
                const float* __restrict__ b11,   // [32]
                const float* __restrict__ fcb,   // [64]
                float*       __restrict__ out,   // [B,64]
                int batch)
{
    // region A: featC[32][129] (16512B) then reused as a1[U][39][16] (9984B)
    __shared__ __align__(16) float regA[32 * FPITCH];
    // region B: winner scratch (624B) -> y[128][3][16] (24576B) -> z[U][39][32] (19968B)
    __shared__ __align__(16) float regB[MAXJ * 3 * C31];
    __shared__ __align__(16) float p[U * FCD];          // 2560B
    __shared__ __align__(16) float w11s[C31 * C11];     // [ic][oc] 2048B
    __shared__ float b11s[C11];
    __shared__ int   jOf[U * G];                        // global slot id per (u,cell)
    __shared__ int   vehG[MAXJ];
    __shared__ int   totCnt;

    float* const featC = regA;
    float* const a1    = regA;
    float* const y     = regB;
    float* const z     = regB;

    const int b0  = blockIdx.x * U;
    const int tid = threadIdx.x;
    const int wid = tid >> 5;
    const int lan = tid & 31;

    // ---- init + stage small weights (512 entries under 256 threads: strided!) ----
    if (tid < U * G) jOf[tid] = -1;
    if (tid == 0) totCnt = 0;
    for (int i = tid; i < C31 * C11; i += 256) {        // w11s[ic*32+oc] = w11[oc*16+ic]
        int ic = i >> 5, oc = i & 31;
        w11s[i] = __ldg(w11 + oc * C31 + ic);
    }
    if (tid < C11) b11s[tid] = __ldg(b11 + tid);

    // ---- winners per cell (regB as int scratch) ----
    int* winner = (int*)regB;
    if (tid < U * G) winner[tid] = -1;
    __syncthreads();
    if (tid < U * KN) {
        int u = tid >> 5, k = tid & 31;
        int b = b0 + u;
        if (b < batch) {
            int v = nb[b * KN + k];
            int x = gp[2 * v], yy = gp[2 * v + 1];
            if (x >= 0 && x < GRID_H && yy >= 0 && yy < GRID_W)
                atomicMax(&winner[u * G + x * GRID_W + yy], k);
        }
    }
    __syncthreads();
    if (tid < U * G) {
        int w = winner[tid];
        if (w >= 0) {
            int u = tid / G;
            int v = nb[(b0 + u) * KN + w];
            int j = atomicAdd(&totCnt, 1);
            jOf[tid] = j;
            vehG[j]  = v;
        }
    }
    __syncthreads();
    const int tot    = totCnt;
    const int ntiles = (tot + 31) >> 5;

    // ---- per tile: gather features, conv3x1 partials into y ----
    for (int t = 0; t < ntiles; ++t) {
        const int jBase = t << 5;
        const int nT    = min(32, tot - jBase);

        // gather: nT slots x 128 channels
        for (int i = tid; i < (nT << 7); i += 256) {
            int s = i >> 7, ic = i & 127;
            int v = vehG[jBase + s];
            featC[s * FPITCH + ic] =
                __ldg(enc + (size_t)v * (ENC * TS) + ic * TS + (TS - 1));
        }
        __syncthreads();

        // conv: warp-task c = (kh,ocg) in [0,12), lane = slot in tile
        for (int c = wid; c < 12; c += 8) {
            int kh = c >> 2, ocg = c & 3;
            const float4* wr = (const float4*)wT + (kh << 9) + ocg;
            const float*  fr = featC + lan * FPITCH;
            float4 acc = make_float4(0.f, 0.f, 0.f, 0.f);
            #pragma unroll 4
            for (int ic = 0; ic < ENC; ++ic) {
                float4 wv = __ldg(wr + (ic << 2));   // uniform across lanes
                float  f  = fr[ic];
                acc.x += f * wv.x; acc.y += f * wv.y;
                acc.z += f * wv.z; acc.w += f * wv.w;
            }
            if (lan < nT) {
                float* yo = y + (((jBase + lan) * 3 + kh) << 4) + (ocg << 2);
                yo[0] = acc.x; yo[1] = acc.y; yo[2] = acc.z; yo[3] = acc.w;
            }
        }
        __syncthreads();
    }

    // ---- assemble a1[u][pos][oc] = lrelu(bias + sum_kh y), fixed order ----
    for (int e = tid; e < U * G * C31; e += 256) {
        int u   = e / (G * C31);
        int r   = e - u * (G * C31);
        int pos = r >> 4, oc = r & 15;
        int h = pos / 3, w = pos - h * 3;
        float val = __ldg(b31 + oc);
        #pragma unroll
        for (int dh = -1; dh <= 1; ++dh) {
            int hh = h + dh;
            if ((unsigned)hh < (unsigned)GRID_H) {
                int j = jOf[u * G + hh * 3 + w];
                if (j >= 0)
                    val += y[((j * 3 + (dh + 1)) << 4) + oc];
            }
        }
        a1[e] = lrelu(val);
    }
    __syncthreads();

    // ---- conv1x1 + lrelu -> z[u][pos][32oc]  (z aliases y; y dead) ----
    for (int t = tid; t < U * G * 8; t += 256) {
        int u   = t / (G * 8);
        int r   = t - u * (G * 8);
        int pos = r >> 3, ocg = r & 7;
        const float* ar = a1 + u * (G * C31) + (pos << 4);
        float4 acc = *(const float4*)(b11s + (ocg << 2));
        #pragma unroll
        for (int ic = 0; ic < C31; ++ic) {
            float  f  = ar[ic];
            float4 wv = ((const float4*)w11s)[(ic << 3) + ocg];
            acc.x += f * wv.x; acc.y += f * wv.y;
            acc.z += f * wv.z; acc.w += f * wv.w;
        }
        float* zo = z + u * (G * C11) + (pos << 5) + (ocg << 2);
        zo[0] = lrelu(acc.x); zo[1] = lrelu(acc.y);
        zo[2] = lrelu(acc.z); zo[3] = lrelu(acc.w);
    }
    __syncthreads();

    // ---- 3x3/3 maxpool: p[u][oc2*5+ph] ----
    for (int t = tid; t < U * FCD; t += 256) {
        int u   = t / FCD;
        int r   = t - u * FCD;
        int oc2 = r / 5, ph = r - oc2 * 5;
        float m = -3.4e38f;
        int h1 = min(3 * ph + 3, GRID_H);
        for (int h = 3 * ph; h < h1; ++h)
            #pragma unroll
            for (int w = 0; w < 3; ++w)
                m = fmaxf(m, z[u * (G * C11) + ((h * 3 + w) << 5) + oc2]);
        p[t] = m;
    }
    __syncthreads();

    // ---- FC 160 -> 64: lane-contiguous fcwT reads (1 line / warp-iter) ----
    {
        int u = tid >> 6, o = tid & 63;
        int b = b0 + u;
        if (b < batch) {
            float acc = __ldg(fcb + o);
            const float* pu = p + u * FCD;
            #pragma unroll 8
            for (int f = 0; f < FCD; ++f)
                acc += __ldg(fcwT + (f << 6) + o) * pu[f];
            out[b * SOCD + o] = lrelu(acc);
        }
    }
}

} // namespace

extern "C" void kernel_launch(void* const* d_in, const int* in_sizes, int n_in,
                              void* d_out, int out_size)
{
    const float* enc = (const float*)d_in[0];
    const int*   nb  = (const int*)  d_in[1];
    const int*   gp  = (const int*)  d_in[2];
    const float* w31 = (const float*)d_in[3];
    const float* b31 = (const float*)d_in[4];
    const float* w11 = (const float*)d_in[5];
    const float* b11 = (const float*)d_in[6];
    const float* fcw = (const float*)d_in[7];
    const float* fcb = (const float*)d_in[8];
    float* out = (float*)d_out;

    const int batch = in_sizes[1] / KN;   // 8192

    prep_kernel<<<(FCD * SOCD + 255) / 256, 256>>>(w31, fcw);
    csp_kernel<<<(batch + U - 1) / U, 256>>>(enc, nb, gp, b31, w11, b11, fcb, out, batch);
}

// round 7
// speedup vs baseline: 2.2610x; 1.2028x over previous
#include <cuda_runtime.h>

// Round 7: occupancy + redundancy.
//  - 6 blocks/SM: smem 47->36KB (per-tile y + incremental a1; conv1x1 fused
//    into pool with lane=oc2 broadcast reads; no z buffer), launch_bounds(256,6).
//  - FC cooperative: each fcwT line read once (warp=(o-half,f-quarter)),
//    p stored [f][u] so batch dim is one uniform float4 LDS; smem reduction.
//  - conv3x1 unchanged (lane=slot, uniform weight LDG).
namespace {

constexpr int GRID_H = 13;
constexpr int GRID_W = 3;
constexpr int G      = GRID_H * GRID_W;   // 39
constexpr int ENC    = 128;
constexpr int TS     = 16;
constexpr int C31    = 16;
constexpr int C11    = 32;
constexpr int SOCD   = 64;
constexpr int KN     = 32;
constexpr int U      = 4;                 // batches per block
constexpr int FPITCH = 129;
constexpr int MAXJ   = U * KN;            // 128 worst-case slots
constexpr int FCD    = 160;

__device__ __align__(16) float wT[3 * ENC * C31];     // [kh][ic][oc16]
__device__ __align__(16) float fcwT[FCD * SOCD];      // [f][o]

__device__ __forceinline__ float lrelu(float x) { return x > 0.0f ? x : 0.1f * x; }

__global__ void prep_kernel(const float* __restrict__ w31,
                            const float* __restrict__ fcw)
{
    int i = blockIdx.x * 256 + threadIdx.x;
    if (i < 3 * ENC * C31) {
        int kh = i >> 11;
        int r  = i & 2047;
        int ic = r >> 4, oc = r & 15;
        wT[i] = w31[(oc * ENC + ic) * 3 + kh];
    }
    if (i < FCD * SOCD) {
        int f = i >> 6, o = i & 63;
        fcwT[i] = fcw[o * FCD + f];
    }
}

__global__ __launch_bounds__(256, 6)
void csp_kernel(const float* __restrict__ enc,   // [N_VEH,128,16]
                const int*   __restrict__ nb,    // [B,32]
                const int*   __restrict__ gp,    // [N_VEH,2]
                const float* __restrict__ b31,   // [16]
                const float* __restrict__ w11,   // [32,16]
                const float* __restrict__ b11,   // [32]
                const float* __restrict__ fcb,   // [64]
                float*       __restrict__ out,   // [B,64]
                int batch)
{
    __shared__ __align__(16) float featC[32 * FPITCH];   // 16512B; later red[4][64][4] (4KB)
    __shared__ __align__(16) float yT[32 * 3 * C31];     // 6144B per-tile partials; later p[160][4]
    __shared__ __align__(16) float a1[U * G * C31];      // 9984B; winner ints at start
    __shared__ __align__(16) float w11s[C31 * C11];      // [ic][oc] 2048B
    __shared__ float b31s[C31];
    __shared__ float b11s[C11];
    __shared__ int   jOf[U * G];
    __shared__ int   vehG[MAXJ];
    __shared__ int   totCnt;

    const int b0  = blockIdx.x * U;
    const int tid = threadIdx.x;
    const int wid = tid >> 5;
    const int lan = tid & 31;

    // ---- stage small weights / init ----
    for (int i = tid; i < C31 * C11; i += 256) {          // w11s[ic*32+oc]
        int ic = i >> 5, oc = i & 31;
        w11s[i] = __ldg(w11 + oc * C31 + ic);
    }
    if (tid < C31) b31s[tid] = __ldg(b31 + tid);
    if (tid < C11) b11s[tid] = __ldg(b11 + tid);
    if (tid < U * G) jOf[tid] = -1;
    if (tid == 0) totCnt = 0;
    int* winner = (int*)a1;                               // a1 region as winner scratch
    if (tid < U * G) winner[tid] = -1;
    __syncthreads();

    // ---- winners per cell ----
    if (tid < U * KN) {
        int u = tid >> 5, k = tid & 31;
        int b = b0 + u;
        if (b < batch) {
            int v = nb[b * KN + k];
            int x = __ldg(gp + 2 * v), yy = __ldg(gp + 2 * v + 1);
            if (x >= 0 && x < GRID_H && yy >= 0 && yy < GRID_W)
                atomicMax(&winner[u * G + x * GRID_W + yy], k);
        }
    }
    __syncthreads();
    if (tid < U * G) {
        int w = winner[tid];
        if (w >= 0) {
            int u = tid / G;
            int v = nb[(b0 + u) * KN + w];
            int j = atomicAdd(&totCnt, 1);
            jOf[tid] = j;
            vehG[j]  = v;
        }
    }
    __syncthreads();
    const int tot    = totCnt;
    const int ntiles = (tot + 31) >> 5;

    // ---- init a1 = bias (winner scratch dead) ----
    for (int e = tid; e < U * G * C31; e += 256)
        a1[e] = b31s[e & 15];
    __syncthreads();

    // ---- tiles: gather -> conv3x1 partials -> accumulate a1 ----
    for (int t = 0; t < ntiles; ++t) {
        const int  jBase = t << 5;
        const int  nT    = min(32, tot - jBase);
        const bool last  = (t == ntiles - 1);

        for (int i = tid; i < (nT << 7); i += 256) {
            int s = i >> 7, ic = i & 127;
            int v = vehG[jBase + s];
            featC[s * FPITCH + ic] =
                __ldg(enc + (size_t)v * (ENC * TS) + ic * TS + (TS - 1));
        }
        __syncthreads();

        for (int c = wid; c < 12; c += 8) {
            int kh = c >> 2, ocg = c & 3;
            const float4* wr = (const float4*)wT + (kh << 9) + ocg;
            const float*  fr = featC + lan * FPITCH;
            float4 acc = make_float4(0.f, 0.f, 0.f, 0.f);
            #pragma unroll 4
            for (int ic = 0; ic < ENC; ++ic) {
                float4 wv = __ldg(wr + (ic << 2));   // uniform across lanes
                float  f  = fr[ic];
                acc.x += f * wv.x; acc.y += f * wv.y;
                acc.z += f * wv.z; acc.w += f * wv.w;
            }
            if (lan < nT)
                *(float4*)(yT + lan * 48 + (kh << 4) + (ocg << 2)) = acc;
        }
        __syncthreads();

        // accumulate partials of this tile into a1 (same thread owns each elem
        // every tile -> deterministic); lrelu on the last tile.
        for (int e = tid; e < U * G * C31; e += 256) {
            int u   = e / (G * C31);
            int r   = e - u * (G * C31);
            int pos = r >> 4, oc = r & 15;
            int h = pos / 3, w = pos - h * 3;
            float val = a1[e];
            #pragma unroll
            for (int dh = -1; dh <= 1; ++dh) {
                int hh = h + dh;
                if ((unsigned)hh < (unsigned)GRID_H) {
                    int j = jOf[u * G + hh * 3 + w];
                    int s = j - jBase;
                    if (s >= 0 && s < nT)
                        val += yT[s * 48 + ((dh + 1) << 4) + oc];
                }
            }
            a1[e] = last ? lrelu(val) : val;
        }
        __syncthreads();
    }
    if (ntiles == 0) {      // degenerate: no occupied cells anywhere
        for (int e = tid; e < U * G * C31; e += 256)
            a1[e] = lrelu(a1[e]);
        __syncthreads();
    }

    // ---- conv1x1 + lrelu + 3x3/3 maxpool, fused. warp-task=(u,ph), lane=oc2 ----
    float* const p = yT;   // p[f][u], f = oc2*5+ph (flatten order); yT dead
    for (int wt = wid; wt < U * 5; wt += 8) {
        int u = wt / 5, ph = wt - u * 5;
        float wr[16];
        #pragma unroll
        for (int ic = 0; ic < 16; ++ic) wr[ic] = w11s[(ic << 5) + lan];
        float bias = b11s[lan];
        float m = -3.4e38f;
        int h1 = min(3 * ph + 3, GRID_H);
        for (int h = 3 * ph; h < h1; ++h) {
            #pragma unroll
            for (int w = 0; w < 3; ++w) {
                const float* ar = a1 + u * (G * C31) + ((h * 3 + w) << 4);
                float s = bias;
                #pragma unroll
                for (int ic = 0; ic < 16; ++ic)
                    s += ar[ic] * wr[ic];        // ar broadcast (1 wf)
                m = fmaxf(m, lrelu(s));
            }
        }
        p[((lan * 5 + ph) << 2) + u] = m;
    }
    __syncthreads();

    // ---- FC 160->64 cooperative: warp=(o-half, f-quarter) ----
    float* const red = featC;                    // red[fr][o][u], 4KB; featC dead
    {
        int orr = wid & 1, fq = wid >> 1;
        int o = (orr << 5) + lan;
        float a0 = 0.f, a1s = 0.f, a2 = 0.f, a3 = 0.f;
        int f0 = fq * 40;
        #pragma unroll 8
        for (int f = f0; f < f0 + 40; ++f) {
            float  wv = __ldg(fcwT + (f << 6) + o);        // 1 line / warp
            float4 pv = *(const float4*)(p + (f << 2));    // uniform
            a0 += wv * pv.x; a1s += wv * pv.y;
            a2 += wv * pv.z; a3  += wv * pv.w;
        }
        *(float4*)(red + ((fq << 6) + o) * 4) = make_float4(a0, a1s, a2, a3);
    }
    __syncthreads();
    {
        int u = tid >> 6, o = tid & 63;
        int b = b0 + u;
        if (b < batch) {
            float acc = __ldg(fcb + o);
            #pragma unroll
            for (int fq = 0; fq < 4; ++fq)
                acc += red[((fq << 6) + o) * 4 + u];
            out[b * SOCD + o] = lrelu(acc);
        }
    }
}

} // namespace

extern "C" void kernel_launch(void* const* d_in, const int* in_sizes, int n_in,
                              void* d_out, int out_size)
{
    const float* enc = (const float*)d_in[0];
    const int*   nb  = (const int*)  d_in[1];
    const int*   gp  = (const int*)  d_in[2];
    const float* w31 = (const float*)d_in[3];
    const float* b31 = (const float*)d_in[4];
    const float* w11 = (const float*)d_in[5];
    const float* b11 = (const float*)d_in[6];
    const float* fcw = (const float*)d_in[7];
    const float* fcb = (const float*)d_in[8];
    float* out = (float*)d_out;

    const int batch = in_sizes[1] / KN;   // 8192

    prep_kernel<<<(FCD * SOCD + 255) / 256, 256>>>(w31, fcw);
    csp_kernel<<<(batch + U - 1) / U, 256>>>(enc, nb, gp, b31, w11, b11, fcb, out, batch);
}